// round 13
// baseline (speedup 1.0000x reference)
#include <cuda_runtime.h>
#include <math.h>

// L=8,B=8,N=4,HIN=1024,D=1024,NH=16,KVH=8,HD=64,FF=3072,W=1024,DOUT=1024, M=B*N=32

__device__ float g_scratch[425984];
#define OFF_H    0
#define OFF_XH   32768
#define OFF_XL   65536
#define OFF_QKV  98304
#define OFF_ATTH 163840
#define OFF_ATTL 196608
#define OFF_GU   229376

__device__ __forceinline__ unsigned tf32_rna(float v) {
    unsigned r; asm("cvt.rna.tf32.f32 %0, %1;" : "=r"(r) : "f"(v)); return r;
}

#define MMA_TF32(C, A0, A1, A2, A3, B0, B1)                                  \
    asm("mma.sync.aligned.m16n8k8.row.col.f32.tf32.tf32.f32 "                \
        "{%0,%1,%2,%3},{%4,%5,%6,%7},{%8,%9},{%0,%1,%2,%3};"                 \
        : "+f"(C[0]), "+f"(C[1]), "+f"(C[2]), "+f"(C[3])                      \
        : "r"(A0), "r"(A1), "r"(A2), "r"(A3), "r"(B0), "r"(B1))

// prep: zero h row + tf32-split hidden row into xh/xl
__global__ void prep_kernel(const float* __restrict__ hidden, float* __restrict__ h,
                            float* __restrict__ xh, float* __restrict__ xl) {
    int m = blockIdx.x, tid = threadIdx.x;
    ((float4*)(h + m * 1024))[tid] = make_float4(0.f, 0.f, 0.f, 0.f);
    float4 v = ((const float4*)(hidden + m * 1024))[tid];
    float vv[4] = {v.x, v.y, v.z, v.w};
#pragma unroll
    for (int j = 0; j < 4; j++) {
        unsigned hb = tf32_rna(vv[j]);
        xh[m * 1024 + tid * 4 + j] = __uint_as_float(hb);
        xl[m * 1024 + tid * 4 + j] = __uint_as_float(tf32_rna(vv[j] - __uint_as_float(hb)));
    }
}

// ---- RMSNorm over 1024 cols -> tf32 hi/lo split (+ zero an accumulator buffer)
__global__ void rms_kernel(const float* __restrict__ hin, const float* __restrict__ w,
                           float* __restrict__ xh, float* __restrict__ xl,
                           float* __restrict__ zbuf, int zn4) {
    __shared__ float sw[8];
    int m = blockIdx.x, tid = threadIdx.x;
    float4 v = ((const float4*)(hin + m * 1024))[tid];
    float ss = v.x * v.x + v.y * v.y + v.z * v.z + v.w * v.w;
    for (int o = 16; o; o >>= 1) ss += __shfl_xor_sync(~0u, ss, o);
    if ((tid & 31) == 0) sw[tid >> 5] = ss;
    __syncthreads();
    if (tid < 32) {
        float z = (tid < 8) ? sw[tid] : 0.f;
        for (int o = 4; o; o >>= 1) z += __shfl_xor_sync(~0u, z, o);
        if (tid == 0) sw[0] = z;
    }
    __syncthreads();
    float rs = rsqrtf(sw[0] * (1.0f / 1024.0f) + 1e-6f);
    float4 wv = ((const float4*)w)[tid];
    float vv[4] = {v.x * rs * wv.x, v.y * rs * wv.y, v.z * rs * wv.z, v.w * rs * wv.w};
#pragma unroll
    for (int j = 0; j < 4; j++) {
        unsigned hb = tf32_rna(vv[j]);
        xh[m * 1024 + tid * 4 + j] = __uint_as_float(hb);
        xl[m * 1024 + tid * 4 + j] = __uint_as_float(tf32_rna(vv[j] - __uint_as_float(hb)));
    }
    if (zbuf) {
        float4 zz = make_float4(0.f, 0.f, 0.f, 0.f);
        for (int i = m * 256 + tid; i < zn4; i += 8192) ((float4*)zbuf)[i] = zz;
    }
}

// ---- skinny GEMM v10 (tensor-core 3xTF32, fully async staging)
// out[32,*] (+)= x[32,K] @ W[K,*]; 128 cols/block; 8 warps, warp = 16 cols x 32
// rows via 4x m16n8k8, 3 mma/k8 (hi*hi + hi*lo + lo*hi). Weights cp.async S-stage
// pipeline; x pre-split (RAW=false: cp.async from xh/xl) or LDG+SwiGLU (RAW=true).
// Split-K grid.y, fp32 atomic epilogue. 3 col segments. omode=1 -> [B,DOUT,N].
template<int KC, int S, bool RAW>
__global__ __launch_bounds__(256, 4) void gemmtc(
    const float* __restrict__ bh, const float* __restrict__ bl,
    const float* __restrict__ xraw, int xstride, int uoff,
    const float* __restrict__ w0, const float* __restrict__ w1, const float* __restrict__ w2,
    int ld0, int ld1, int ld2, int b1, int b2,
    float* __restrict__ out, int ostride, int omode) {
    constexpr int TOT = KC / 8;
    constexpr int XR = KC + 4;
    __shared__ __align__(16) unsigned xh[32 * XR];
    __shared__ __align__(16) unsigned xl[32 * XR];
    __shared__ __align__(16) float ws[S][8 * 136];

    int tid = threadIdx.x, wp = tid >> 5, lane = tid & 31;
    int g = lane >> 2, t = lane & 3;
    int kk = tid >> 5, cc = tid & 31;
    int col0 = blockIdx.x * 128, kbase = blockIdx.y * KC;
    const float* w; int ld, c0;
    if (col0 < b1)      { w = w0; ld = ld0; c0 = col0; }
    else if (col0 < b2) { w = w1; ld = ld1; c0 = col0 - b1; }
    else                { w = w2; ld = ld2; c0 = col0 - b2; }

    auto fill = [&](int s, int st) {
        const float* src = w + (size_t)(kbase + st * 8 + kk) * ld + c0 + cc * 4;
        unsigned sd = (unsigned)__cvta_generic_to_shared(&ws[s][kk * 136 + cc * 4]);
        asm volatile("cp.async.cg.shared.global [%0], [%1], 16;" :: "r"(sd), "l"(src));
    };

    if (!RAW) {
        // x tile via cp.async: first group in the pipeline
#pragma unroll
        for (int i = tid; i < 32 * (KC / 4); i += 256) {
            int m = i / (KC / 4), k4 = i % (KC / 4);
            const float* sh = bh + m * xstride + kbase + k4 * 4;
            const float* sl = bl + m * xstride + kbase + k4 * 4;
            unsigned dh = (unsigned)__cvta_generic_to_shared(&xh[m * XR + k4 * 4]);
            unsigned dl = (unsigned)__cvta_generic_to_shared(&xl[m * XR + k4 * 4]);
            asm volatile("cp.async.cg.shared.global [%0], [%1], 16;" :: "r"(dh), "l"(sh));
            asm volatile("cp.async.cg.shared.global [%0], [%1], 16;" :: "r"(dl), "l"(sl));
        }
        asm volatile("cp.async.commit_group;");
    }

#pragma unroll
    for (int s = 0; s < S - 1; s++) {
        if (s < TOT) fill(s, s);
        asm volatile("cp.async.commit_group;");
    }

    if (RAW) {
#pragma unroll 4
        for (int idx = tid; idx < 32 * KC; idx += 256) {
            int m = idx / KC, k = idx - m * KC;
            float v = xraw[m * xstride + kbase + k];
            float uu = xraw[m * xstride + uoff + kbase + k];
            v = (v / (1.0f + expf(-v))) * uu;
            unsigned hb = tf32_rna(v);
            xh[m * XR + k] = hb;
            xl[m * XR + k] = tf32_rna(v - __uint_as_float(hb));
        }
    }

    float c[4][4];
#pragma unroll
    for (int mt = 0; mt < 4; mt++)
#pragma unroll
        for (int i = 0; i < 4; i++) c[mt][i] = 0.f;

    int cw = wp * 16;

#pragma unroll 1
    for (int st = 0; st < TOT; st++) {
        asm volatile("cp.async.wait_group %0;" :: "n"(S - 2));
        __syncthreads();
        int ns = st + S - 1;
        if (ns < TOT) fill(ns % S, ns);
        asm volatile("cp.async.commit_group;");
        const float* wsp = ws[st % S];

        float wv0 = wsp[t * 136 + cw + g];
        float wv1 = wsp[t * 136 + cw + g + 8];
        float wv2 = wsp[(t + 4) * 136 + cw + g];
        float wv3 = wsp[(t + 4) * 136 + cw + g + 8];
        unsigned ah0 = tf32_rna(wv0), ah1 = tf32_rna(wv1);
        unsigned ah2 = tf32_rna(wv2), ah3 = tf32_rna(wv3);
        unsigned al0 = tf32_rna(wv0 - __uint_as_float(ah0));
        unsigned al1 = tf32_rna(wv1 - __uint_as_float(ah1));
        unsigned al2 = tf32_rna(wv2 - __uint_as_float(ah2));
        unsigned al3 = tf32_rna(wv3 - __uint_as_float(ah3));

        int kb = st * 8;
#pragma unroll
        for (int mt = 0; mt < 4; mt++) {
            int xr = (mt * 8 + g) * XR + kb;
            unsigned bh0 = xh[xr + t], bh1 = xh[xr + t + 4];
            unsigned bl0 = xl[xr + t], bl1 = xl[xr + t + 4];
            MMA_TF32(c[mt], ah0, ah1, ah2, ah3, bl0, bl1);
            MMA_TF32(c[mt], al0, al1, al2, al3, bh0, bh1);
            MMA_TF32(c[mt], ah0, ah1, ah2, ah3, bh0, bh1);
        }
    }

#pragma unroll
    for (int mt = 0; mt < 4; mt++) {
        int r0 = mt * 8 + 2 * t;
        int cA = col0 + cw + g;
#pragma unroll
        for (int i = 0; i < 4; i++) {
            int row = r0 + (i & 1);
            int col = cA + (i >> 1) * 8;
            if (omode == 0) {
                atomicAdd(out + row * ostride + col, c[mt][i]);
            } else {
                int bb = row >> 2, tt = row & 3;
                atomicAdd(out + (bb * 1024 + col) * 4 + tt, c[mt][i]);
            }
        }
    }
}

// ---- fused attention: rope/rms q,k + cache write + slab copy + attention
// epilogue writes tf32 hi/lo split of the result (feeds Wo gemm directly)
__global__ __launch_bounds__(256) void attn2(
    const float* __restrict__ qkvb, const float* __restrict__ pk,
    const float* __restrict__ pv, const float* __restrict__ qn,
    const float* __restrict__ kn, float* __restrict__ ks, float* __restrict__ vs,
    float* __restrict__ atth, float* __restrict__ attl, int l) {
    __shared__ __align__(16) float qs[4][64];
    __shared__ __align__(16) float knew[4][64];
    __shared__ __align__(16) float vnew[4][64];
    __shared__ float ps[4][1024];
    __shared__ float red[2048];
    __shared__ float smax[4], ssum[4], swarp[8];
    int tid = threadIdx.x, b = blockIdx.x >> 4, h = blockIdx.x & 15, kvh = h >> 1;
    int wid = tid >> 5, lane = tid & 31;
    size_t slab = ((size_t)((l * 8 + b) * 8 + kvh)) * 65536;

    {
        int t = wid & 3, m = b * 4 + t;
        float invf = 1.0f / powf(1.0e6f, (float)lane * (1.0f / 32.0f));
        float angf = (float)(1024 + t) * invf;
        double ad = (double)angf;
        float cc = (float)cos(ad), sn = (float)sin(ad);
        if (wid < 4) {
            const float* base = qkvb + m * 2048 + h * 64;
            float a = base[lane], bb2 = base[lane + 32];
            float sq = a * a + bb2 * bb2;
            for (int o = 16; o; o >>= 1) sq += __shfl_xor_sync(~0u, sq, o);
            float rs = rsqrtf(sq * (1.0f / 64.0f) + 1e-6f);
            float ya = a * rs * qn[lane], yb = bb2 * rs * qn[lane + 32];
            qs[t][lane] = ya * cc - yb * sn;
            qs[t][lane + 32] = yb * cc + ya * sn;
        } else {
            const float* base = qkvb + m * 2048 + 1024 + kvh * 64;
            float a = base[lane], bb2 = base[lane + 32];
            float sq = a * a + bb2 * bb2;
            for (int o = 16; o; o >>= 1) sq += __shfl_xor_sync(~0u, sq, o);
            float rs = rsqrtf(sq * (1.0f / 64.0f) + 1e-6f);
            float ya = a * rs * kn[lane], yb = bb2 * rs * kn[lane + 32];
            float oa = ya * cc - yb * sn, ob = yb * cc + ya * sn;
            knew[t][lane] = oa; knew[t][lane + 32] = ob;
            const float* vb = qkvb + m * 2048 + 1536 + kvh * 64;
            float va = vb[lane], v2 = vb[lane + 32];
            vnew[t][lane] = va; vnew[t][lane + 32] = v2;
            size_t off = slab + (size_t)(1020 + t) * 64;
            if ((h & 1) == 0) { ks[off + lane] = oa; ks[off + lane + 32] = ob; }
            else              { vs[off + lane] = va; vs[off + lane + 32] = v2; }
        }
    }
    __syncthreads();

    const float* kcp = pk + slab + 256;
    bool doK = ((h & 1) == 0);
    float* kout = ks + slab;

    for (int r = 0; r < 4; r++) {
        int j = tid + (r << 8);
        const float4* kp4 = (j < 1020) ? (const float4*)(kcp + (size_t)j * 64)
                                       : (const float4*)(&knew[j - 1020][0]);
        float4* ko4 = (float4*)(kout + (size_t)j * 64);
        bool wr = doK && (j < 1020);
        float a0 = 0.f, a1 = 0.f, a2 = 0.f, a3 = 0.f;
#pragma unroll
        for (int d4 = 0; d4 < 16; d4++) {
            float4 kv = kp4[d4];
            if (wr) ko4[d4] = kv;
            float4 q0 = *(const float4*)&qs[0][d4 * 4];
            float4 q1 = *(const float4*)&qs[1][d4 * 4];
            float4 q2 = *(const float4*)&qs[2][d4 * 4];
            float4 q3 = *(const float4*)&qs[3][d4 * 4];
            a0 += kv.x * q0.x + kv.y * q0.y + kv.z * q0.z + kv.w * q0.w;
            a1 += kv.x * q1.x + kv.y * q1.y + kv.z * q1.z + kv.w * q1.w;
            a2 += kv.x * q2.x + kv.y * q2.y + kv.z * q2.z + kv.w * q2.w;
            a3 += kv.x * q3.x + kv.y * q3.y + kv.z * q3.z + kv.w * q3.w;
        }
        ps[0][j] = a0 * 0.125f + ((j <= 1020) ? 0.f : -10000.f);
        ps[1][j] = a1 * 0.125f + ((j <= 1021) ? 0.f : -10000.f);
        ps[2][j] = a2 * 0.125f + ((j <= 1022) ? 0.f : -10000.f);
        ps[3][j] = a3 * 0.125f;
    }
    __syncthreads();

    for (int t = 0; t < 4; t++) {
        float v = -1e30f;
        for (int j = tid; j < 1024; j += 256) v = fmaxf(v, ps[t][j]);
        for (int o = 16; o; o >>= 1) v = fmaxf(v, __shfl_xor_sync(~0u, v, o));
        if (lane == 0) swarp[wid] = v;
        __syncthreads();
        if (tid == 0) { float z = swarp[0]; for (int i = 1; i < 8; i++) z = fmaxf(z, swarp[i]); smax[t] = z; }
        __syncthreads();
    }
    float psum[4] = {0.f, 0.f, 0.f, 0.f};
    for (int t = 0; t < 4; t++)
        for (int j = tid; j < 1024; j += 256) {
            float e = expf(ps[t][j] - smax[t]);
            ps[t][j] = e; psum[t] += e;
        }
    for (int t = 0; t < 4; t++) {
        float v = psum[t];
        for (int o = 16; o; o >>= 1) v += __shfl_xor_sync(~0u, v, o);
        if (lane == 0) swarp[wid] = v;
        __syncthreads();
        if (tid == 0) { float z = 0.f; for (int i = 0; i < 8; i++) z += swarp[i]; ssum[t] = z; }
        __syncthreads();
    }
    {
        int u = tid & 31, s = tid >> 5;
        const float2* vcp = (const float2*)(pv + slab + 256);
        float2* vout = (float2*)(vs + slab);
        bool doV = ((h & 1) != 0);
        float oo[4][2] = {{0,0},{0,0},{0,0},{0,0}};
        for (int j = s * 128; j < s * 128 + 128; j++) {
            float2 v2 = (j < 1020) ? vcp[(size_t)j * 32 + u]
                                   : ((const float2*)vnew)[(j - 1020) * 32 + u];
            if (doV && j < 1020) vout[(size_t)j * 32 + u] = v2;
#pragma unroll
            for (int t = 0; t < 4; t++) { oo[t][0] += ps[t][j] * v2.x; oo[t][1] += ps[t][j] * v2.y; }
        }
#pragma unroll
        for (int t = 0; t < 4; t++) {
            red[((s * 4 + t) * 32 + u) * 2 + 0] = oo[t][0];
            red[((s * 4 + t) * 32 + u) * 2 + 1] = oo[t][1];
        }
    }
    __syncthreads();
    {
        int t = tid >> 6, d = tid & 63, u = d >> 1, c = d & 1;
        float z = 0.f;
#pragma unroll
        for (int si = 0; si < 8; si++) z += red[((si * 4 + t) * 32 + u) * 2 + c];
        z /= ssum[t];
        unsigned hb = tf32_rna(z);
        int idx = (b * 4 + t) * 1024 + h * 64 + d;
        atth[idx] = __uint_as_float(hb);
        attl[idx] = __uint_as_float(tf32_rna(z - __uint_as_float(hb)));
    }
}

extern "C" void kernel_launch(void* const* d_in, const int* in_sizes, int n_in,
                              void* d_out, int out_size) {
    const float* hidden = (const float*)d_in[0];
    const float* pk     = (const float*)d_in[1];
    const float* pv     = (const float*)d_in[2];
    const float* Win    = (const float*)d_in[3];
    const float* Wout   = (const float*)d_in[4];
    const float* normw  = (const float*)d_in[5];
    const float* Wq     = (const float*)d_in[6];
    const float* Wk     = (const float*)d_in[7];
    const float* Wv     = (const float*)d_in[8];
    const float* Wo     = (const float*)d_in[9];
    const float* ln1    = (const float*)d_in[10];
    const float* ln2    = (const float*)d_in[11];
    const float* qn     = (const float*)d_in[12];
    const float* kn     = (const float*)d_in[13];
    const float* Wg     = (const float*)d_in[14];
    const float* Wu     = (const float*)d_in[15];
    const float* Wd     = (const float*)d_in[16];

    float* outp = (float*)d_out;
    float* oh  = outp;
    float* oks = outp + 32768;
    float* ovs = outp + 32768 + 33554432;

    float* sc = 0;
    cudaGetSymbolAddress((void**)&sc, g_scratch);
    float* h    = sc + OFF_H;
    float* xh   = sc + OFF_XH;
    float* xl   = sc + OFF_XL;
    float* qkv  = sc + OFF_QKV;
    float* atth = sc + OFF_ATTH;
    float* attl = sc + OFF_ATTL;
    float* gu   = sc + OFF_GU;
    const int BIG = 1 << 30;

    prep_kernel<<<32, 256>>>(hidden, h, xh, xl);
    gemmtc<64, 5, false><<<dim3(8, 16), 256>>>(xh, xl, 0, 1024, 0,
        Win, Win, Win, 1024, 1024, 1024, BIG, BIG, h, 1024, 0);

    for (int l = 0; l < 8; l++) {
        rms_kernel<<<32, 256>>>(h, ln1 + l * 1024, xh, xl, qkv, 16384);
        gemmtc<64, 5, false><<<dim3(16, 16), 256>>>(xh, xl, 0, 1024, 0,
            Wq + (size_t)l * 1048576, Wk + (size_t)l * 524288, Wv + (size_t)l * 524288,
            1024, 512, 512, 1024, 1536, qkv, 2048, 0);
        attn2<<<128, 256>>>(qkv, pk, pv, qn + l * 64, kn + l * 64, oks, ovs, atth, attl, l);
        gemmtc<64, 5, false><<<dim3(8, 16), 256>>>(atth, attl, 0, 1024, 0,
            Wo + (size_t)l * 1048576, Wo, Wo, 1024, 1024, 1024, BIG, BIG, h, 1024, 0);
        rms_kernel<<<32, 256>>>(h, ln2 + l * 1024, xh, xl, gu, 49152);
        gemmtc<64, 5, false><<<dim3(48, 16), 256>>>(xh, xl, 0, 1024, 0,
            Wg + (size_t)l * 3145728, Wu + (size_t)l * 3145728, Wu,
            3072, 3072, 3072, 3072, BIG, gu, 6144, 0);
        gemmtc<64, 5, true><<<dim3(8, 48), 256>>>(0, 0, gu, 6144, 3072,
            Wd + (size_t)l * 3145728, Wd, Wd, 1024, 1024, 1024, BIG, BIG, h, 1024, 0);
    }

    rms_kernel<<<32, 256>>>(h, normw, xh, xl, oh, 8192);
    gemmtc<64, 5, false><<<dim3(8, 16), 256>>>(xh, xl, 0, 1024, 0,
        Wout, Wout, Wout, 1024, 1024, 1024, BIG, BIG, oh, 1024, 1);
}

// round 14
// speedup vs baseline: 1.0223x; 1.0223x over previous
#include <cuda_runtime.h>
#include <math.h>

// L=8,B=8,N=4,HIN=1024,D=1024,NH=16,KVH=8,HD=64,FF=3072,W=1024,DOUT=1024, M=B*N=32

__device__ float g_scratch[425984];
#define OFF_H    0
#define OFF_XH   32768
#define OFF_XL   65536
#define OFF_QKV  98304
#define OFF_ATTH 163840
#define OFF_ATTL 196608
#define OFF_GU   229376

__device__ __forceinline__ unsigned tf32_rna(float v) {
    unsigned r; asm("cvt.rna.tf32.f32 %0, %1;" : "=r"(r) : "f"(v)); return r;
}

#define MMA_TF32(C, A0, A1, A2, A3, B0, B1)                                  \
    asm("mma.sync.aligned.m16n8k8.row.col.f32.tf32.tf32.f32 "                \
        "{%0,%1,%2,%3},{%4,%5,%6,%7},{%8,%9},{%0,%1,%2,%3};"                 \
        : "+f"(C[0]), "+f"(C[1]), "+f"(C[2]), "+f"(C[3])                      \
        : "r"(A0), "r"(A1), "r"(A2), "r"(A3), "r"(B0), "r"(B1))

// prep: zero h row + tf32-split hidden row into xh/xl
__global__ void prep_kernel(const float* __restrict__ hidden, float* __restrict__ h,
                            float* __restrict__ xh, float* __restrict__ xl) {
    int m = blockIdx.x, tid = threadIdx.x;
    ((float4*)(h + m * 1024))[tid] = make_float4(0.f, 0.f, 0.f, 0.f);
    float4 v = ((const float4*)(hidden + m * 1024))[tid];
    float vv[4] = {v.x, v.y, v.z, v.w};
#pragma unroll
    for (int j = 0; j < 4; j++) {
        unsigned hb = tf32_rna(vv[j]);
        xh[m * 1024 + tid * 4 + j] = __uint_as_float(hb);
        xl[m * 1024 + tid * 4 + j] = __uint_as_float(tf32_rna(vv[j] - __uint_as_float(hb)));
    }
}

// ---- RMSNorm over 1024 cols -> tf32 hi/lo split (+ zero an accumulator buffer)
__global__ void rms_kernel(const float* __restrict__ hin, const float* __restrict__ w,
                           float* __restrict__ xh, float* __restrict__ xl,
                           float* __restrict__ zbuf, int zn4) {
    __shared__ float sw[8];
    int m = blockIdx.x, tid = threadIdx.x;
    float4 v = ((const float4*)(hin + m * 1024))[tid];
    float ss = v.x * v.x + v.y * v.y + v.z * v.z + v.w * v.w;
    for (int o = 16; o; o >>= 1) ss += __shfl_xor_sync(~0u, ss, o);
    if ((tid & 31) == 0) sw[tid >> 5] = ss;
    __syncthreads();
    if (tid < 32) {
        float z = (tid < 8) ? sw[tid] : 0.f;
        for (int o = 4; o; o >>= 1) z += __shfl_xor_sync(~0u, z, o);
        if (tid == 0) sw[0] = z;
    }
    __syncthreads();
    float rs = rsqrtf(sw[0] * (1.0f / 1024.0f) + 1e-6f);
    float4 wv = ((const float4*)w)[tid];
    float vv[4] = {v.x * rs * wv.x, v.y * rs * wv.y, v.z * rs * wv.z, v.w * rs * wv.w};
#pragma unroll
    for (int j = 0; j < 4; j++) {
        unsigned hb = tf32_rna(vv[j]);
        xh[m * 1024 + tid * 4 + j] = __uint_as_float(hb);
        xl[m * 1024 + tid * 4 + j] = __uint_as_float(tf32_rna(vv[j] - __uint_as_float(hb)));
    }
    if (zbuf) {
        float4 zz = make_float4(0.f, 0.f, 0.f, 0.f);
        for (int i = m * 256 + tid; i < zn4; i += 8192) ((float4*)zbuf)[i] = zz;
    }
}

// ---- skinny GEMM v11 (tensor-core 3xTF32, 8KB stages, dynamic smem)
// out[32,*] (+)= x[32,K] @ W[K,*]; 128 cols/block; 8 warps, warp = 16 cols x 32
// rows via 4x m16n8k8, 3 mma/k8. Weight pipeline: S stages x 16 k-rows (8KB),
// fewer/bigger stages amortize wait_group+bar skew. x pre-split (cp.async) or
// LDG+SwiGLU (RAW). Split-K grid.y, fp32 atomic epilogue. 3 col segments.
// omode=1 -> transposed epilogue [B,DOUT,N].
template<int KC, int S, bool RAW>
__global__ __launch_bounds__(256, 4) void gemmtc(
    const float* __restrict__ bh, const float* __restrict__ bl,
    const float* __restrict__ xraw, int xstride, int uoff,
    const float* __restrict__ w0, const float* __restrict__ w1, const float* __restrict__ w2,
    int ld0, int ld1, int ld2, int b1, int b2,
    float* __restrict__ out, int ostride, int omode) {
    constexpr int TOT = KC / 16;               // 16 k-rows per stage
    constexpr int XR = KC + 4;
    extern __shared__ __align__(16) float dsm[];
    float* ws = dsm;                            // S * 16 * 136 floats
    unsigned* xh = (unsigned*)(dsm + S * 16 * 136);
    unsigned* xl = xh + 32 * XR;

    int tid = threadIdx.x, wp = tid >> 5, lane = tid & 31;
    int g = lane >> 2, t = lane & 3;
    int col0 = blockIdx.x * 128, kbase = blockIdx.y * KC;
    const float* w; int ld, c0;
    if (col0 < b1)      { w = w0; ld = ld0; c0 = col0; }
    else if (col0 < b2) { w = w1; ld = ld1; c0 = col0 - b1; }
    else                { w = w2; ld = ld2; c0 = col0 - b2; }

    // fill one 16-row stage: 512 16B-chunks, 2 per thread
    auto fill = [&](int s, int st) {
#pragma unroll
        for (int j = 0; j < 2; j++) {
            int c = tid + j * 256;
            int kk = c >> 5, cc = c & 31;
            const float* src = w + (size_t)(kbase + st * 16 + kk) * ld + c0 + cc * 4;
            unsigned sd = (unsigned)__cvta_generic_to_shared(&ws[(s * 16 + kk) * 136 + cc * 4]);
            asm volatile("cp.async.cg.shared.global [%0], [%1], 16;" :: "r"(sd), "l"(src));
        }
    };

    if (!RAW) {
        // x tile via cp.async: first group
#pragma unroll
        for (int i = tid; i < 32 * (KC / 4); i += 256) {
            int m = i / (KC / 4), k4 = i % (KC / 4);
            const float* sh = bh + m * xstride + kbase + k4 * 4;
            const float* sl = bl + m * xstride + kbase + k4 * 4;
            unsigned dh = (unsigned)__cvta_generic_to_shared(&xh[m * XR + k4 * 4]);
            unsigned dl = (unsigned)__cvta_generic_to_shared(&xl[m * XR + k4 * 4]);
            asm volatile("cp.async.cg.shared.global [%0], [%1], 16;" :: "r"(dh), "l"(sh));
            asm volatile("cp.async.cg.shared.global [%0], [%1], 16;" :: "r"(dl), "l"(sl));
        }
        asm volatile("cp.async.commit_group;");
    }

#pragma unroll
    for (int s = 0; s < S - 1; s++) {
        if (s < TOT) fill(s, s);
        asm volatile("cp.async.commit_group;");
    }

    if (RAW) {
#pragma unroll 4
        for (int idx = tid; idx < 32 * KC; idx += 256) {
            int m = idx / KC, k = idx - m * KC;
            float v = xraw[m * xstride + kbase + k];
            float uu = xraw[m * xstride + uoff + kbase + k];
            v = (v / (1.0f + expf(-v))) * uu;
            unsigned hb = tf32_rna(v);
            xh[m * XR + k] = hb;
            xl[m * XR + k] = tf32_rna(v - __uint_as_float(hb));
        }
    }

    float c[4][4];
#pragma unroll
    for (int mt = 0; mt < 4; mt++)
#pragma unroll
        for (int i = 0; i < 4; i++) c[mt][i] = 0.f;

    int cw = wp * 16;

#pragma unroll 1
    for (int st = 0; st < TOT; st++) {
        asm volatile("cp.async.wait_group %0;" :: "n"(S - 2));
        __syncthreads();
        int ns = st + S - 1;
        if (ns < TOT) fill(ns % S, ns);
        asm volatile("cp.async.commit_group;");
        const float* wsp = &ws[(st % S) * 16 * 136];

#pragma unroll
        for (int j = 0; j < 2; j++) {          // two k8 sub-steps per stage
            float wv0 = wsp[(j * 8 + t) * 136 + cw + g];
            float wv1 = wsp[(j * 8 + t) * 136 + cw + g + 8];
            float wv2 = wsp[(j * 8 + t + 4) * 136 + cw + g];
            float wv3 = wsp[(j * 8 + t + 4) * 136 + cw + g + 8];
            unsigned ah0 = tf32_rna(wv0), ah1 = tf32_rna(wv1);
            unsigned ah2 = tf32_rna(wv2), ah3 = tf32_rna(wv3);
            unsigned al0 = tf32_rna(wv0 - __uint_as_float(ah0));
            unsigned al1 = tf32_rna(wv1 - __uint_as_float(ah1));
            unsigned al2 = tf32_rna(wv2 - __uint_as_float(ah2));
            unsigned al3 = tf32_rna(wv3 - __uint_as_float(ah3));

            int kb = st * 16 + j * 8;
#pragma unroll
            for (int mt = 0; mt < 4; mt++) {
                int xr = (mt * 8 + g) * XR + kb;
                unsigned bh0 = xh[xr + t], bh1 = xh[xr + t + 4];
                unsigned bl0 = xl[xr + t], bl1 = xl[xr + t + 4];
                MMA_TF32(c[mt], ah0, ah1, ah2, ah3, bl0, bl1);
                MMA_TF32(c[mt], al0, al1, al2, al3, bh0, bh1);
                MMA_TF32(c[mt], ah0, ah1, ah2, ah3, bh0, bh1);
            }
        }
    }

#pragma unroll
    for (int mt = 0; mt < 4; mt++) {
        int r0 = mt * 8 + 2 * t;
        int cA = col0 + cw + g;
#pragma unroll
        for (int i = 0; i < 4; i++) {
            int row = r0 + (i & 1);
            int col = cA + (i >> 1) * 8;
            if (omode == 0) {
                atomicAdd(out + row * ostride + col, c[mt][i]);
            } else {
                int bb = row >> 2, tt = row & 3;
                atomicAdd(out + (bb * 1024 + col) * 4 + tt, c[mt][i]);
            }
        }
    }
}

// ---- fused attention: rope/rms q,k + cache write + slab copy + attention
__global__ __launch_bounds__(256) void attn2(
    const float* __restrict__ qkvb, const float* __restrict__ pk,
    const float* __restrict__ pv, const float* __restrict__ qn,
    const float* __restrict__ kn, float* __restrict__ ks, float* __restrict__ vs,
    float* __restrict__ atth, float* __restrict__ attl, int l) {
    __shared__ __align__(16) float qs[4][64];
    __shared__ __align__(16) float knew[4][64];
    __shared__ __align__(16) float vnew[4][64];
    __shared__ float ps[4][1024];
    __shared__ float red[2048];
    __shared__ float smax[4], ssum[4], swarp[8];
    int tid = threadIdx.x, b = blockIdx.x >> 4, h = blockIdx.x & 15, kvh = h >> 1;
    int wid = tid >> 5, lane = tid & 31;
    size_t slab = ((size_t)((l * 8 + b) * 8 + kvh)) * 65536;

    {
        int t = wid & 3, m = b * 4 + t;
        float invf = 1.0f / powf(1.0e6f, (float)lane * (1.0f / 32.0f));
        float angf = (float)(1024 + t) * invf;
        double ad = (double)angf;
        float cc = (float)cos(ad), sn = (float)sin(ad);
        if (wid < 4) {
            const float* base = qkvb + m * 2048 + h * 64;
            float a = base[lane], bb2 = base[lane + 32];
            float sq = a * a + bb2 * bb2;
            for (int o = 16; o; o >>= 1) sq += __shfl_xor_sync(~0u, sq, o);
            float rs = rsqrtf(sq * (1.0f / 64.0f) + 1e-6f);
            float ya = a * rs * qn[lane], yb = bb2 * rs * qn[lane + 32];
            qs[t][lane] = ya * cc - yb * sn;
            qs[t][lane + 32] = yb * cc + ya * sn;
        } else {
            const float* base = qkvb + m * 2048 + 1024 + kvh * 64;
            float a = base[lane], bb2 = base[lane + 32];
            float sq = a * a + bb2 * bb2;
            for (int o = 16; o; o >>= 1) sq += __shfl_xor_sync(~0u, sq, o);
            float rs = rsqrtf(sq * (1.0f / 64.0f) + 1e-6f);
            float ya = a * rs * kn[lane], yb = bb2 * rs * kn[lane + 32];
            float oa = ya * cc - yb * sn, ob = yb * cc + ya * sn;
            knew[t][lane] = oa; knew[t][lane + 32] = ob;
            const float* vb = qkvb + m * 2048 + 1536 + kvh * 64;
            float va = vb[lane], v2 = vb[lane + 32];
            vnew[t][lane] = va; vnew[t][lane + 32] = v2;
            size_t off = slab + (size_t)(1020 + t) * 64;
            if ((h & 1) == 0) { ks[off + lane] = oa; ks[off + lane + 32] = ob; }
            else              { vs[off + lane] = va; vs[off + lane + 32] = v2; }
        }
    }
    __syncthreads();

    const float* kcp = pk + slab + 256;
    bool doK = ((h & 1) == 0);
    float* kout = ks + slab;

    for (int r = 0; r < 4; r++) {
        int j = tid + (r << 8);
        const float4* kp4 = (j < 1020) ? (const float4*)(kcp + (size_t)j * 64)
                                       : (const float4*)(&knew[j - 1020][0]);
        float4* ko4 = (float4*)(kout + (size_t)j * 64);
        bool wr = doK && (j < 1020);
        float a0 = 0.f, a1 = 0.f, a2 = 0.f, a3 = 0.f;
#pragma unroll
        for (int d4 = 0; d4 < 16; d4++) {
            float4 kv = kp4[d4];
            if (wr) ko4[d4] = kv;
            float4 q0 = *(const float4*)&qs[0][d4 * 4];
            float4 q1 = *(const float4*)&qs[1][d4 * 4];
            float4 q2 = *(const float4*)&qs[2][d4 * 4];
            float4 q3 = *(const float4*)&qs[3][d4 * 4];
            a0 += kv.x * q0.x + kv.y * q0.y + kv.z * q0.z + kv.w * q0.w;
            a1 += kv.x * q1.x + kv.y * q1.y + kv.z * q1.z + kv.w * q1.w;
            a2 += kv.x * q2.x + kv.y * q2.y + kv.z * q2.z + kv.w * q2.w;
            a3 += kv.x * q3.x + kv.y * q3.y + kv.z * q3.z + kv.w * q3.w;
        }
        ps[0][j] = a0 * 0.125f + ((j <= 1020) ? 0.f : -10000.f);
        ps[1][j] = a1 * 0.125f + ((j <= 1021) ? 0.f : -10000.f);
        ps[2][j] = a2 * 0.125f + ((j <= 1022) ? 0.f : -10000.f);
        ps[3][j] = a3 * 0.125f;
    }
    __syncthreads();

    for (int t = 0; t < 4; t++) {
        float v = -1e30f;
        for (int j = tid; j < 1024; j += 256) v = fmaxf(v, ps[t][j]);
        for (int o = 16; o; o >>= 1) v = fmaxf(v, __shfl_xor_sync(~0u, v, o));
        if (lane == 0) swarp[wid] = v;
        __syncthreads();
        if (tid == 0) { float z = swarp[0]; for (int i = 1; i < 8; i++) z = fmaxf(z, swarp[i]); smax[t] = z; }
        __syncthreads();
    }
    float psum[4] = {0.f, 0.f, 0.f, 0.f};
    for (int t = 0; t < 4; t++)
        for (int j = tid; j < 1024; j += 256) {
            float e = expf(ps[t][j] - smax[t]);
            ps[t][j] = e; psum[t] += e;
        }
    for (int t = 0; t < 4; t++) {
        float v = psum[t];
        for (int o = 16; o; o >>= 1) v += __shfl_xor_sync(~0u, v, o);
        if (lane == 0) swarp[wid] = v;
        __syncthreads();
        if (tid == 0) { float z = 0.f; for (int i = 0; i < 8; i++) z += swarp[i]; ssum[t] = z; }
        __syncthreads();
    }
    {
        int u = tid & 31, s = tid >> 5;
        const float2* vcp = (const float2*)(pv + slab + 256);
        float2* vout = (float2*)(vs + slab);
        bool doV = ((h & 1) != 0);
        float oo[4][2] = {{0,0},{0,0},{0,0},{0,0}};
        for (int j = s * 128; j < s * 128 + 128; j++) {
            float2 v2 = (j < 1020) ? vcp[(size_t)j * 32 + u]
                                   : ((const float2*)vnew)[(j - 1020) * 32 + u];
            if (doV && j < 1020) vout[(size_t)j * 32 + u] = v2;
#pragma unroll
            for (int t = 0; t < 4; t++) { oo[t][0] += ps[t][j] * v2.x; oo[t][1] += ps[t][j] * v2.y; }
        }
#pragma unroll
        for (int t = 0; t < 4; t++) {
            red[((s * 4 + t) * 32 + u) * 2 + 0] = oo[t][0];
            red[((s * 4 + t) * 32 + u) * 2 + 1] = oo[t][1];
        }
    }
    __syncthreads();
    {
        int t = tid >> 6, d = tid & 63, u = d >> 1, c = d & 1;
        float z = 0.f;
#pragma unroll
        for (int si = 0; si < 8; si++) z += red[((si * 4 + t) * 32 + u) * 2 + c];
        z /= ssum[t];
        unsigned hb = tf32_rna(z);
        int idx = (b * 4 + t) * 1024 + h * 64 + d;
        atth[idx] = __uint_as_float(hb);
        attl[idx] = __uint_as_float(tf32_rna(z - __uint_as_float(hb)));
    }
}

extern "C" void kernel_launch(void* const* d_in, const int* in_sizes, int n_in,
                              void* d_out, int out_size) {
    const float* hidden = (const float*)d_in[0];
    const float* pk     = (const float*)d_in[1];
    const float* pv     = (const float*)d_in[2];
    const float* Win    = (const float*)d_in[3];
    const float* Wout   = (const float*)d_in[4];
    const float* normw  = (const float*)d_in[5];
    const float* Wq     = (const float*)d_in[6];
    const float* Wk     = (const float*)d_in[7];
    const float* Wv     = (const float*)d_in[8];
    const float* Wo     = (const float*)d_in[9];
    const float* ln1    = (const float*)d_in[10];
    const float* ln2    = (const float*)d_in[11];
    const float* qn     = (const float*)d_in[12];
    const float* kn     = (const float*)d_in[13];
    const float* Wg     = (const float*)d_in[14];
    const float* Wu     = (const float*)d_in[15];
    const float* Wd     = (const float*)d_in[16];

    float* outp = (float*)d_out;
    float* oh  = outp;
    float* oks = outp + 32768;
    float* ovs = outp + 32768 + 33554432;

    float* sc = 0;
    cudaGetSymbolAddress((void**)&sc, g_scratch);
    float* h    = sc + OFF_H;
    float* xh   = sc + OFF_XH;
    float* xl   = sc + OFF_XL;
    float* qkv  = sc + OFF_QKV;
    float* atth = sc + OFF_ATTH;
    float* attl = sc + OFF_ATTL;
    float* gu   = sc + OFF_GU;
    const int BIG = 1 << 30;

    // dynamic smem: ws S*16*136 floats + xh/xl 32*(KC+4) each
    const int DSM = 4 * 16 * 136 * 4 + 2 * 32 * 68 * 4;   // 52224 B for KC=64,S=4
    cudaFuncSetAttribute(gemmtc<64, 4, false>,
                         cudaFuncAttributeMaxDynamicSharedMemorySize, DSM);
    cudaFuncSetAttribute(gemmtc<64, 4, true>,
                         cudaFuncAttributeMaxDynamicSharedMemorySize, DSM);

    prep_kernel<<<32, 256>>>(hidden, h, xh, xl);
    gemmtc<64, 4, false><<<dim3(8, 16), 256, DSM>>>(xh, xl, 0, 1024, 0,
        Win, Win, Win, 1024, 1024, 1024, BIG, BIG, h, 1024, 0);

    for (int l = 0; l < 8; l++) {
        rms_kernel<<<32, 256>>>(h, ln1 + l * 1024, xh, xl, qkv, 16384);
        gemmtc<64, 4, false><<<dim3(16, 16), 256, DSM>>>(xh, xl, 0, 1024, 0,
            Wq + (size_t)l * 1048576, Wk + (size_t)l * 524288, Wv + (size_t)l * 524288,
            1024, 512, 512, 1024, 1536, qkv, 2048, 0);
        attn2<<<128, 256>>>(qkv, pk, pv, qn + l * 64, kn + l * 64, oks, ovs, atth, attl, l);
        gemmtc<64, 4, false><<<dim3(8, 16), 256, DSM>>>(atth, attl, 0, 1024, 0,
            Wo + (size_t)l * 1048576, Wo, Wo, 1024, 1024, 1024, BIG, BIG, h, 1024, 0);
        rms_kernel<<<32, 256>>>(h, ln2 + l * 1024, xh, xl, gu, 49152);
        gemmtc<64, 4, false><<<dim3(48, 16), 256, DSM>>>(xh, xl, 0, 1024, 0,
            Wg + (size_t)l * 3145728, Wu + (size_t)l * 3145728, Wu,
            3072, 3072, 3072, 3072, BIG, gu, 6144, 0);
        gemmtc<64, 4, true><<<dim3(8, 48), 256, DSM>>>(0, 0, gu, 6144, 3072,
            Wd + (size_t)l * 3145728, Wd, Wd, 1024, 1024, 1024, BIG, BIG, h, 1024, 0);
    }

    rms_kernel<<<32, 256>>>(h, normw, xh, xl, oh, 8192);
    gemmtc<64, 4, false><<<dim3(8, 16), 256, DSM>>>(xh, xl, 0, 1024, 0,
        Wout, Wout, Wout, 1024, 1024, 1024, BIG, BIG, oh, 1024, 1);
}